// round 6
// baseline (speedup 1.0000x reference)
#include <cuda_runtime.h>
#include <math.h>

#define PATCH    32
#define HP       256
#define WP       256
#define NPATCH   (HP * WP)        // 65536
#define IMG_W4   2048             // float4 per image row
#define PPB      64               // patches per CTA (8 warps x 8 patches)
#define NGRID1   (NPATCH / PPB)   // 1024 CTAs

// ln(0.04 * sqrt(2*pi)) = -2.2999372...
#define LOG_NORM_CONST (-2.2999372199f)

// Per-CTA partials: (pos_sum, neg_sum, pos_count)
__device__ float4 g_part[NGRID1];
__device__ unsigned int g_count;   // zero-init; reset by last CTA each run

// Fused kernel. Each warp owns 8 horizontally-adjacent patches and streams
// all 64 float4 loads (8 row-groups x 8 patches) into 8 register
// accumulators with NO shuffles inside the load stream. Per row-group the
// warp covers 4 rows x 1KB contiguous. Epilogue: 8 xor-reduces, lanes 0-7
// compute the pos/neg terms, fixed-order combine, last-CTA finish.
__global__ void __launch_bounds__(256, 6)
fused_kernel(const float* __restrict__ x, const float* __restrict__ tmask,
             float* __restrict__ out) {
    const int tid = threadIdx.x;
    const int w   = tid >> 5;            // warp 0..7
    const int l   = tid & 31;            // lane
    const int lrow = l >> 3;             // 0..3 base row
    const int lq   = l & 7;              // float4 within 128B patch-row

    const int p_cta = blockIdx.x * PPB;  // first patch of CTA (same patch row)
    const int ph    = p_cta >> 8;        // patch row
    const int pw    = (p_cta & 255) + w * 8;  // this warp's first patch col

    // base address in float4 units
    const float4* bp = (const float4*)x
                     + (size_t)(ph * PATCH + lrow) * IMG_W4
                     + (size_t)pw * 8 + lq;

    float acc[8];
    #pragma unroll
    for (int t = 0; t < 8; t++) acc[t] = 0.0f;

    #pragma unroll
    for (int k = 0; k < 8; k++) {                 // row-group (rows lrow+4k)
        const float4* rp = bp + (size_t)k * 4 * IMG_W4;
        #pragma unroll
        for (int t = 0; t < 8; t++) {             // 8 independent loads
            const float4 v = __ldcs(rp + t * 8);
            acc[t] += (v.x + v.y) + (v.z + v.w);
        }
    }

    // Epilogue: full xor reduce each accumulator (every lane gets each sum).
    #pragma unroll
    for (int o = 16; o > 0; o >>= 1) {
        #pragma unroll
        for (int t = 0; t < 8; t++)
            acc[t] += __shfl_xor_sync(0xffffffffu, acc[t], o);
    }

    // Lane t (t<8) takes patch t's sum (static selection, no dynamic index).
    float msum = acc[0];
    #pragma unroll
    for (int t = 1; t < 8; t++)
        if (l == t) msum = acc[t];

    float ps = 0.0f, ns = 0.0f, pc = 0.0f;
    if (l < 8) {
        const float mean = msum * (1.0f / (PATCH * PATCH));
        const float z = (mean - 0.34f) * 25.0f;
        const float logpdf = -0.5f * z * z - LOG_NORM_CONST;
        const float pos_t = -logf(expf(logpdf) + 1e-6f);
        const float neg_t = mean * mean;
        const float mk = (tmask[p_cta + w * 8 + l] >= 0.5f) ? 1.0f : 0.0f;
        ps = pos_t * mk;
        ns = neg_t * (1.0f - mk);
        pc = mk;
    }

    // Reduce lanes 0..7 (offsets 1,2,4 stay within the 8-lane group).
    #pragma unroll
    for (int o = 4; o > 0; o >>= 1) {
        ps += __shfl_xor_sync(0xffffffffu, ps, o);
        ns += __shfl_xor_sync(0xffffffffu, ns, o);
        pc += __shfl_xor_sync(0xffffffffu, pc, o);
    }

    __shared__ float3 pr[8];
    if (l == 0) pr[w] = make_float3(ps, ns, pc);
    __syncthreads();

    __shared__ bool s_last;
    if (tid < 8) {
        float3 a = pr[tid];
        float cps = a.x, cns = a.y, cpc = a.z;
        #pragma unroll
        for (int o = 4; o > 0; o >>= 1) {
            cps += __shfl_xor_sync(0xffu, cps, o);
            cns += __shfl_xor_sync(0xffu, cns, o);
            cpc += __shfl_xor_sync(0xffu, cpc, o);
        }
        if (tid == 0) {
            g_part[blockIdx.x] = make_float4(cps, cns, cpc, 0.0f);
            __threadfence();
            const unsigned int old = atomicAdd(&g_count, 1u);
            s_last = (old == NGRID1 - 1);
        }
    }
    __syncthreads();

    if (!s_last) return;

    // ---- Last CTA: reduce all 1024 partials in fixed order (deterministic) ----
    float fps = 0.0f, fns = 0.0f, fpc = 0.0f;
    #pragma unroll
    for (int k = 0; k < NGRID1 / 256; k++) {      // 4 independent loads
        const float4 p = g_part[tid + k * 256];
        fps += p.x; fns += p.y; fpc += p.z;
    }

    #pragma unroll
    for (int o = 16; o > 0; o >>= 1) {
        fps += __shfl_xor_sync(0xffffffffu, fps, o);
        fns += __shfl_xor_sync(0xffffffffu, fns, o);
        fpc += __shfl_xor_sync(0xffffffffu, fpc, o);
    }

    __shared__ float f_ps[8], f_ns[8], f_pc[8];
    if (l == 0) { f_ps[w] = fps; f_ns[w] = fns; f_pc[w] = fpc; }
    __syncthreads();

    if (tid < 8) {
        fps = f_ps[tid]; fns = f_ns[tid]; fpc = f_pc[tid];
        #pragma unroll
        for (int o = 4; o > 0; o >>= 1) {
            fps += __shfl_xor_sync(0xffu, fps, o);
            fns += __shfl_xor_sync(0xffu, fns, o);
            fpc += __shfl_xor_sync(0xffu, fpc, o);
        }
        if (tid == 0) {
            const float fnc = (float)NPATCH - fpc;
            out[0] = fps / fpc + fns / fnc;
            g_count = 0;                  // reset for next graph replay
        }
    }
}

extern "C" void kernel_launch(void* const* d_in, const int* in_sizes, int n_in,
                              void* d_out, int out_size) {
    const float* unet  = (const float*)d_in[0];   // [1,1,8192,8192] fp32
    const float* tmask = (const float*)d_in[1];   // [1,256,256] fp32
    float* out = (float*)d_out;

    fused_kernel<<<NGRID1, 256>>>(unet, tmask, out);
}

// round 7
// speedup vs baseline: 1.0623x; 1.0623x over previous
#include <cuda_runtime.h>
#include <math.h>

#define PATCH    32
#define HP       256
#define WP       256
#define NPATCH   (HP * WP)        // 65536
#define IMG_W    8192
#define IMG_W4   (IMG_W / 4)      // 2048 float4 per row
#define PPB      16               // patches per CTA (8 warps x 2 iters)
#define NGRID1   (NPATCH / PPB)   // 4096 CTAs

// ln(0.04 * sqrt(2*pi)) = -2.2999372...
#define LOG_NORM_CONST (-2.2999372199f)

// Per-CTA partials: (pos_sum, neg_sum, pos_count, unused)
__device__ float4 g_part[NGRID1];
__device__ unsigned int g_count;   // zero-init; reset by last CTA each run

// Fused kernel, round-5 proven body with finer CTA granularity for wave
// balance. Warp-per-patch: lanes cover 4 rows x 8 float4; k-loop issues 8
// independent loads per patch (MLP 8). 2 patches per warp, 16 per CTA.
__global__ void __launch_bounds__(256, 8)
fused_kernel(const float* __restrict__ x, const float* __restrict__ tmask,
             float* __restrict__ out) {
    const int tid = threadIdx.x;
    const int w   = tid >> 5;            // warp 0..7
    const int l   = tid & 31;            // lane
    const int p_base = blockIdx.x * PPB; // first patch of this CTA

    __shared__ float means[PPB];

    const int lrow = l >> 3;             // 0..3 base row
    const int lq   = l & 7;              // float4 within 128B row segment

    #pragma unroll
    for (int t = 0; t < 2; t++) {
        const int p  = p_base + t * 8 + w;
        const int ph = p >> 8;
        const int pw = p & 255;
        const float4* p4 = (const float4*)x
                         + (size_t)(ph * PATCH) * IMG_W4 + (size_t)pw * 8;

        float s = 0.0f;
        #pragma unroll
        for (int k = 0; k < 8; k++) {    // 8 independent loads in flight
            const float4 v = __ldcs(&p4[(size_t)(lrow + 4 * k) * IMG_W4 + lq]);
            s += (v.x + v.y) + (v.z + v.w);
        }

        #pragma unroll
        for (int o = 16; o > 0; o >>= 1)
            s += __shfl_xor_sync(0xffffffffu, s, o);

        if (l == 0) means[t * 8 + w] = s * (1.0f / (PATCH * PATCH));
    }
    __syncthreads();

    // Tail: warp 0 computes 16 terms on lanes 0..15, reduces, emits partial.
    __shared__ bool s_last;
    if (w == 0) {
        float ps = 0.0f, ns = 0.0f, pc = 0.0f;
        if (l < PPB) {
            const float mean = means[l];
            const float z = (mean - 0.34f) * 25.0f;
            const float logpdf = -0.5f * z * z - LOG_NORM_CONST;
            const float pos_t = -logf(expf(logpdf) + 1e-6f);
            const float neg_t = mean * mean;
            const float mk = (tmask[p_base + l] >= 0.5f) ? 1.0f : 0.0f;
            ps = pos_t * mk;
            ns = neg_t * (1.0f - mk);
            pc = mk;
        }
        #pragma unroll
        for (int o = 8; o > 0; o >>= 1) {
            ps += __shfl_xor_sync(0xffffffffu, ps, o);
            ns += __shfl_xor_sync(0xffffffffu, ns, o);
            pc += __shfl_xor_sync(0xffffffffu, pc, o);
        }
        if (l == 0) {
            g_part[blockIdx.x] = make_float4(ps, ns, pc, 0.0f);
            __threadfence();
            const unsigned int old = atomicAdd(&g_count, 1u);
            s_last = (old == NGRID1 - 1);
        }
    }
    __syncthreads();

    if (!s_last) return;

    // ---- Last CTA: reduce 4096 partials in fixed order (deterministic) ----
    float fps = 0.0f, fns = 0.0f, fpc = 0.0f;
    #pragma unroll
    for (int k = 0; k < NGRID1 / 256; k++) {      // 16 independent loads
        const float4 p = g_part[tid + k * 256];
        fps += p.x; fns += p.y; fpc += p.z;
    }

    #pragma unroll
    for (int o = 16; o > 0; o >>= 1) {
        fps += __shfl_xor_sync(0xffffffffu, fps, o);
        fns += __shfl_xor_sync(0xffffffffu, fns, o);
        fpc += __shfl_xor_sync(0xffffffffu, fpc, o);
    }

    __shared__ float f_ps[8], f_ns[8], f_pc[8];
    if (l == 0) { f_ps[w] = fps; f_ns[w] = fns; f_pc[w] = fpc; }
    __syncthreads();

    if (tid < 8) {
        fps = f_ps[tid]; fns = f_ns[tid]; fpc = f_pc[tid];
        #pragma unroll
        for (int o = 4; o > 0; o >>= 1) {
            fps += __shfl_xor_sync(0xffu, fps, o);
            fns += __shfl_xor_sync(0xffu, fns, o);
            fpc += __shfl_xor_sync(0xffu, fpc, o);
        }
        if (tid == 0) {
            const float fnc = (float)NPATCH - fpc;
            out[0] = fps / fpc + fns / fnc;
            g_count = 0;                  // reset for next graph replay
        }
    }
}

extern "C" void kernel_launch(void* const* d_in, const int* in_sizes, int n_in,
                              void* d_out, int out_size) {
    const float* unet  = (const float*)d_in[0];   // [1,1,8192,8192] fp32
    const float* tmask = (const float*)d_in[1];   // [1,256,256] fp32
    float* out = (float*)d_out;

    fused_kernel<<<NGRID1, 256>>>(unet, tmask, out);
}